// round 13
// baseline (speedup 1.0000x reference)
#include <cuda_runtime.h>
#include <cuda_bf16.h>
#include <cstdint>

#define NN 50000      // nodes
#define NE 1250000    // edges
#define FD 64         // embed = hidden = 64
#define NR 3          // relations
#define NG 512        // graphs
#define NC 2          // classes

#define NRNN (NR * NN)   // 150000 (rel,dst) segments
#define BKT 64           // bucket capacity (λ=8.33; P(deg>=64) ~ 1e-40)

typedef unsigned int u32;

// ---------------- device scratch (static, allocation-free) ----------------
__device__ float g_h  [NN * FD];        // fp32 node features (layer-1 input)
__device__ float g_h2 [NN * FD];        // fp32 node features (layer-2 input)
__device__ int   g_cnt [NRNN];          // per (rel,dst) in-degree
__device__ int   g_bkt [NRNN * BKT];    // bucketed src ids (38.4 MB)
__device__ float g_pool[NG * FD];       // pooled sums
__device__ int   g_gcnt[NG];            // nodes per graph

// ---------------- helpers ----------------
__device__ __forceinline__ u32 pack2(__nv_bfloat16 a, __nv_bfloat16 b) {
    return (u32)__bfloat16_as_ushort(a) | ((u32)__bfloat16_as_ushort(b) << 16);
}

// split 4 floats into hi/lo bf16 pairs (packed 2-per-u32)
__device__ __forceinline__ void split4(float4 v, u32* hi, u32* lo) {
    __nv_bfloat16 hx = __float2bfloat16(v.x), hy = __float2bfloat16(v.y);
    __nv_bfloat16 hz = __float2bfloat16(v.z), hw = __float2bfloat16(v.w);
    __nv_bfloat16 lx = __float2bfloat16(v.x - __bfloat162float(hx));
    __nv_bfloat16 ly = __float2bfloat16(v.y - __bfloat162float(hy));
    __nv_bfloat16 lz = __float2bfloat16(v.z - __bfloat162float(hz));
    __nv_bfloat16 lw = __float2bfloat16(v.w - __bfloat162float(hw));
    hi[0] = pack2(hx, hy); hi[1] = pack2(hz, hw);
    lo[0] = pack2(lx, ly); lo[1] = pack2(lz, lw);
}

// SW128 swizzle: rows are 128B; 16B-chunk index XORed with (row & 7)
__device__ __forceinline__ u32 swz(u32 row, u32 chunk) {
    return row * 128u + ((chunk ^ (row & 7u)) << 4);
}

__device__ __forceinline__ void ldmA(u32* a, u32 addr) {
    asm volatile("ldmatrix.sync.aligned.m8n8.x4.shared.b16 {%0,%1,%2,%3}, [%4];"
                 : "=r"(a[0]), "=r"(a[1]), "=r"(a[2]), "=r"(a[3]) : "r"(addr));
}
__device__ __forceinline__ void ldmB4(u32* b, u32 addr) {   // two n8 B-frag pairs
    asm volatile("ldmatrix.sync.aligned.m8n8.x4.trans.shared.b16 {%0,%1,%2,%3}, [%4];"
                 : "=r"(b[0]), "=r"(b[1]), "=r"(b[2]), "=r"(b[3]) : "r"(addr));
}
__device__ __forceinline__ void mma16816(float* d, const u32* a, u32 b0, u32 b1) {
    asm volatile("mma.sync.aligned.m16n8k16.row.col.f32.bf16.bf16.f32 "
                 "{%0,%1,%2,%3}, {%4,%5,%6,%7}, {%8,%9}, {%0,%1,%2,%3};"
                 : "+f"(d[0]), "+f"(d[1]), "+f"(d[2]), "+f"(d[3])
                 : "r"(a[0]), "r"(a[1]), "r"(a[2]), "r"(a[3]), "r"(b0), "r"(b1));
}

// ---------------- kernels ----------------

// setup: zero cnt/pool/gcnt + embedding gather (h = emb[x], padding_idx 0)
__global__ void k_setup(const int* __restrict__ x, const float* __restrict__ emb) {
    int tid = blockIdx.x * blockDim.x + threadIdx.x;   // NN*16 threads
    if (tid < NRNN)    g_cnt[tid] = 0;
    if (tid < NG * FD) g_pool[tid] = 0.f;
    if (tid < NG)      g_gcnt[tid] = 0;
    if (tid >= NN * 16) return;
    int n = tid >> 4, c = tid & 15;
    int tok = __ldg(&x[n]);
    float4 v = make_float4(0.f, 0.f, 0.f, 0.f);
    if (tok != 0) v = *(const float4*)(emb + (size_t)tok * FD + c * 4);
    *(float4*)(g_h + (size_t)n * FD + c * 4) = v;
}

// single-pass CSR: count + bucket-fill; also per-graph node counts
__global__ void k_fill(const int* __restrict__ src, const int* __restrict__ dst,
                       const int* __restrict__ et, const int* __restrict__ batch) {
    int e = blockIdx.x * blockDim.x + threadIdx.x;
    if (e < NN) atomicAdd(&g_gcnt[__ldg(&batch[e])], 1);
    if (e >= NE) return;
    int idx = __ldg(&et[e]) * NN + __ldg(&dst[e]);
    int pos = atomicAdd(&g_cnt[idx], 1);
    if (pos < BKT) g_bkt[idx * BKT + pos] = __ldg(&src[e]);
}

// fused layer: gather (in-kernel bucket means) + tensor-core transform + combine.
//   out = relu([h|a0|a1|a2] @ [Wroot;W0;W1;W2] + b)
// Block: 256 thr = 8 warps, 128-node tile. Per m-plane: stage/gather into sA
// (bf16 hi+lo, SW128), then MMA (split-bf16 3-pass). POOL=false: read g_h,
// write g_h2. POOL=true: read g_h2, red.v2 into g_pool.
#define SW_BYTES (512 * 128)             // weights hi+lo: [2][4 m][64 k] rows
#define SA_BYTES (256 * 128)             // A plane hi+lo: [2][128 row]
#define TR_SMEM (SW_BYTES + SA_BYTES)    // 98304

template <bool POOL>
__global__ __launch_bounds__(256, 2) void k_layer(
    const float* __restrict__ wrel,   // [3][64][64]
    const float* __restrict__ wroot,  // [64][64]
    const float* __restrict__ bias,   // [64]
    const int*   __restrict__ batch)  // [NN] (POOL only)
{
    extern __shared__ char smc[];
    char* sW = smc;                  // swizzled weights hi+lo
    char* sA = smc + SW_BYTES;       // swizzled A plane hi+lo

    const float* __restrict__ hsrc = POOL ? g_h2 : g_h;

    int t = threadIdx.x;
    int lane = t & 31, w = t >> 5;
    int node0 = blockIdx.x * 128;

    // stage weights (once): fp32 -> hi/lo bf16, swizzled 8B stores
    for (int i = t; i < 4096; i += 256) {
        int m = i >> 10, rem = i & 1023;
        int k = rem >> 4, n4 = rem & 15;
        const float* srcp = (m == 0) ? (wroot + k * 64 + n4 * 4)
                                     : (wrel + ((size_t)(m - 1) * 64 + k) * 64 + n4 * 4);
        float4 v = *(const float4*)srcp;
        u32 hi[2], lo[2];
        split4(v, hi, lo);
        u32 rowH = (u32)(m * 64 + k);
        u32 rowL = rowH + 256;
        u32 within = (n4 & 1) * 8;
        *(uint2*)(sW + swz(rowH, (u32)(n4 >> 1)) + within) = make_uint2(hi[0], hi[1]);
        *(uint2*)(sW + swz(rowL, (u32)(n4 >> 1)) + within) = make_uint2(lo[0], lo[1]);
    }

    int qr = lane >> 2;          // fragment row 0..7
    int qc = (lane & 3) * 2;     // fragment col pair base

    float d[8][4];
    #pragma unroll
    for (int nb = 0; nb < 8; nb++) {
        float b0 = __ldg(&bias[nb * 8 + qc]);
        float b1 = __ldg(&bias[nb * 8 + qc + 1]);
        d[nb][0] = b0; d[nb][1] = b1; d[nb][2] = b0; d[nb][3] = b1;
    }

    u32 sA_base = (u32)__cvta_generic_to_shared(sA);
    u32 sW_base = (u32)__cvta_generic_to_shared(sW);
    u32 arow_lo = (u32)(w * 16 + (lane & 15));       // A frag row within split plane
    u32 asel    = (u32)(lane >> 4);                  // chunk half select

    for (int m = 0; m < 4; m++) {
        __syncthreads();     // prior plane's MMA reads done; sA reusable
        if (m == 0) {
            // stage own 128x64 tile from hsrc (fp32, coalesced) -> split -> sA
            #pragma unroll
            for (int j = 0; j < 8; j++) {
                int i = t + j * 256;           // 2048 float4 tasks
                int row = i >> 4, c4 = i & 15;
                int node = node0 + row;
                float4 v = make_float4(0.f, 0.f, 0.f, 0.f);
                if (node < NN) v = *(const float4*)(hsrc + (size_t)node * FD + c4 * 4);
                u32 hi[2], lo[2];
                split4(v, hi, lo);
                u32 within = (c4 & 1) * 8;
                *(uint2*)(sA + swz((u32)row,        (u32)(c4 >> 1)) + within) = make_uint2(hi[0], hi[1]);
                *(uint2*)(sA + swz((u32)row + 128u, (u32)(c4 >> 1)) + within) = make_uint2(lo[0], lo[1]);
            }
        } else {
            // gather plane m: mean over bucket of hsrc[src] for segments
            // p = (m-1)*NN + node0 + seg, seg 0..127; 16 lanes per segment
            #pragma unroll
            for (int j = 0; j < 8; j++) {
                int i = t + j * 256;
                int seg = i >> 4, l4 = i & 15;
                int node = node0 + seg;
                float4 v = make_float4(0.f, 0.f, 0.f, 0.f);
                if (node < NN) {
                    int p = (m - 1) * NN + node;
                    int c = __ldg(&g_cnt[p]);
                    if (c > BKT) c = BKT;
                    const int* bp = g_bkt + (size_t)p * BKT;
                    int e = 0;
                    for (; e + 3 < c; e += 4) {
                        int s0 = __ldg(&bp[e]);
                        int s1 = __ldg(&bp[e + 1]);
                        int s2 = __ldg(&bp[e + 2]);
                        int s3 = __ldg(&bp[e + 3]);
                        float4 a = *(const float4*)(hsrc + (size_t)s0 * FD + l4 * 4);
                        float4 b = *(const float4*)(hsrc + (size_t)s1 * FD + l4 * 4);
                        float4 c2 = *(const float4*)(hsrc + (size_t)s2 * FD + l4 * 4);
                        float4 f = *(const float4*)(hsrc + (size_t)s3 * FD + l4 * 4);
                        v.x += (a.x + b.x) + (c2.x + f.x);
                        v.y += (a.y + b.y) + (c2.y + f.y);
                        v.z += (a.z + b.z) + (c2.z + f.z);
                        v.w += (a.w + b.w) + (c2.w + f.w);
                    }
                    for (; e < c; e++) {
                        int s0 = __ldg(&bp[e]);
                        float4 a = *(const float4*)(hsrc + (size_t)s0 * FD + l4 * 4);
                        v.x += a.x; v.y += a.y; v.z += a.z; v.w += a.w;
                    }
                    float sc = 1.f / fmaxf((float)c, 1.f);
                    v.x *= sc; v.y *= sc; v.z *= sc; v.w *= sc;
                }
                u32 hi[2], lo[2];
                split4(v, hi, lo);
                u32 within = (l4 & 1) * 8;
                *(uint2*)(sA + swz((u32)seg,        (u32)(l4 >> 1)) + within) = make_uint2(hi[0], hi[1]);
                *(uint2*)(sA + swz((u32)seg + 128u, (u32)(l4 >> 1)) + within) = make_uint2(lo[0], lo[1]);
            }
        }
        __syncthreads();     // sA plane ready
        #pragma unroll
        for (int kb = 0; kb < 4; kb++) {
            u32 ah[4], al[4];
            u32 achunk = (u32)(kb * 2) + asel;
            ldmA(ah, sA_base + swz(arow_lo,        achunk));
            ldmA(al, sA_base + swz(arow_lo + 128u, achunk));
            u32 Bh[4][4], Bl[4][4];
            u32 brow = (u32)(m * 64 + kb * 16 + (lane & 15));
            #pragma unroll
            for (int nb2 = 0; nb2 < 4; nb2++) {
                u32 bchunk = (u32)(nb2 * 2) + asel;
                ldmB4(Bh[nb2], sW_base + swz(brow,        bchunk));
                ldmB4(Bl[nb2], sW_base + swz(brow + 256u, bchunk));
            }
            #pragma unroll
            for (int nb2 = 0; nb2 < 4; nb2++) {
                #pragma unroll
                for (int half = 0; half < 2; half++) {
                    float* dd = d[nb2 * 2 + half];
                    u32 bh0 = Bh[nb2][half * 2], bh1 = Bh[nb2][half * 2 + 1];
                    u32 bl0 = Bl[nb2][half * 2], bl1 = Bl[nb2][half * 2 + 1];
                    mma16816(dd, ah, bh0, bh1);
                    mma16816(dd, ah, bl0, bl1);
                    mma16816(dd, al, bh0, bh1);
                }
            }
        }
    }

    // epilogue: relu; POOL: red.v2 into g_pool; else write g_h2 fp32
    int r0 = node0 + w * 16 + qr;
    int r1 = r0 + 8;
    if (POOL) {
        int b0v = (r0 < NN) ? __ldg(&batch[r0]) : 0;
        int b1v = (r1 < NN) ? __ldg(&batch[r1]) : 0;
        #pragma unroll
        for (int nb = 0; nb < 8; nb++) {
            int col = nb * 8 + qc;
            float o0 = fmaxf(d[nb][0], 0.f), o1 = fmaxf(d[nb][1], 0.f);
            float o2 = fmaxf(d[nb][2], 0.f), o3 = fmaxf(d[nb][3], 0.f);
            if (r0 < NN)
                asm volatile("red.global.add.v2.f32 [%0], {%1,%2};"
                             :: "l"(g_pool + (size_t)b0v * FD + col), "f"(o0), "f"(o1) : "memory");
            if (r1 < NN)
                asm volatile("red.global.add.v2.f32 [%0], {%1,%2};"
                             :: "l"(g_pool + (size_t)b1v * FD + col), "f"(o2), "f"(o3) : "memory");
        }
    } else {
        #pragma unroll
        for (int nb = 0; nb < 8; nb++) {
            int col = nb * 8 + qc;
            float o0 = fmaxf(d[nb][0], 0.f), o1 = fmaxf(d[nb][1], 0.f);
            float o2 = fmaxf(d[nb][2], 0.f), o3 = fmaxf(d[nb][3], 0.f);
            if (r0 < NN) *(float2*)(g_h2 + (size_t)r0 * FD + col) = make_float2(o0, o1);
            if (r1 < NN) *(float2*)(g_h2 + (size_t)r1 * FD + col) = make_float2(o2, o3);
        }
    }
}

// final: logits[g] = (pool[g]/max(cnt,1)) @ lin_w + lin_b
__global__ void k_final(const float* __restrict__ lin_w, const float* __restrict__ lin_b,
                        float* __restrict__ out) {
    int g = blockIdx.x;          // 512 blocks
    int f = threadIdx.x;         // 64 threads
    float s = g_pool[g * FD + f] / fmaxf((float)g_gcnt[g], 1.f);
    float p0 = s * lin_w[f * NC + 0];
    float p1 = s * lin_w[f * NC + 1];
    #pragma unroll
    for (int off = 16; off > 0; off >>= 1) {
        p0 += __shfl_down_sync(0xffffffffu, p0, off);
        p1 += __shfl_down_sync(0xffffffffu, p1, off);
    }
    __shared__ float s0[2], s1[2];
    int w = f >> 5;
    if ((f & 31) == 0) { s0[w] = p0; s1[w] = p1; }
    __syncthreads();
    if (f == 0) {
        out[g * NC + 0] = s0[0] + s0[1] + lin_b[0];
        out[g * NC + 1] = s1[0] + s1[1] + lin_b[1];
    }
}

// ---------------- launch ----------------
extern "C" void kernel_launch(void* const* d_in, const int* in_sizes, int n_in,
                              void* d_out, int out_size) {
    const int*   x      = (const int*)  d_in[0];
    const int*   ei     = (const int*)  d_in[1];   // [2, NE]
    const int*   et     = (const int*)  d_in[2];
    const int*   batch  = (const int*)  d_in[3];
    const float* emb    = (const float*)d_in[4];
    const float* w1_rel = (const float*)d_in[5];
    const float* w1_root= (const float*)d_in[6];
    const float* b1     = (const float*)d_in[7];
    const float* w2_rel = (const float*)d_in[8];
    const float* w2_root= (const float*)d_in[9];
    const float* b2     = (const float*)d_in[10];
    const float* lin_w  = (const float*)d_in[11];
    const float* lin_b  = (const float*)d_in[12];
    float* out = (float*)d_out;

    const int* src = ei;
    const int* dst = ei + NE;

    static bool attr_done = false;
    if (!attr_done) {
        cudaFuncSetAttribute(k_layer<false>,
                             cudaFuncAttributeMaxDynamicSharedMemorySize, TR_SMEM);
        cudaFuncSetAttribute(k_layer<true>,
                             cudaFuncAttributeMaxDynamicSharedMemorySize, TR_SMEM);
        attr_done = true;
    }

    const int B = 256;
    int gb_nn16 = (NN * 16 + B - 1) / B;      // 3125
    int gb_ne   = (NE + B - 1) / B;           // 4883
    int gb_tr   = (NN + 127) / 128;           // 391

    k_setup<<<gb_nn16, B>>>(x, emb);
    k_fill<<<gb_ne, B>>>(src, dst, et, batch);

    // layer 1: fused gather + transform (g_h -> g_h2)
    k_layer<false><<<gb_tr, 256, TR_SMEM>>>(w1_rel, w1_root, b1, nullptr);
    // layer 2: fused gather + transform, epilogue pools (g_h2 -> g_pool)
    k_layer<true><<<gb_tr, 256, TR_SMEM>>>(w2_rel, w2_root, b2, batch);

    k_final<<<NG, 64>>>(lin_w, lin_b, out);
}

// round 16
// speedup vs baseline: 1.5130x; 1.5130x over previous
#include <cuda_runtime.h>
#include <cuda_bf16.h>
#include <cuda_fp16.h>
#include <cstdint>

#define NN 50000      // nodes
#define NE 1250000    // edges
#define FD 64         // embed = hidden = 64
#define NR 3          // relations
#define NG 512        // graphs
#define NC 2          // classes

#define NRNN (NR * NN)   // 150000 (rel,dst) segments
#define BKT 64           // bucket capacity (λ=8.33; P(deg>=64) ~ 1e-40)

typedef unsigned int u32;

// ---------------- device scratch (static, allocation-free) ----------------
__device__ __nv_bfloat16 g_Ah [NN * FD];       // h hi-split (m0 plane, bf16)
__device__ __nv_bfloat16 g_Al [NN * FD];       // h lo-split
__device__ __half        g_hh [NN * FD];       // h fp16 (gather input, 6.4 MB)
__device__ __half        g_acch[NR * NN * FD]; // fp16 mean aggregation (19.2 MB)
__device__ int   g_cnt [NRNN];                 // per (rel,dst) in-degree
__device__ int   g_bkt [NRNN * BKT];           // bucketed src ids (38.4 MB)
__device__ float g_pool[NG * FD];              // pooled sums
__device__ int   g_gcnt[NG];                   // nodes per graph

// ---------------- helpers ----------------
__device__ __forceinline__ u32 pack2(__nv_bfloat16 a, __nv_bfloat16 b) {
    return (u32)__bfloat16_as_ushort(a) | ((u32)__bfloat16_as_ushort(b) << 16);
}

// split 4 floats into hi/lo bf16 pairs (packed 2-per-u32)
__device__ __forceinline__ void split4(float4 v, u32* hi, u32* lo) {
    __nv_bfloat16 hx = __float2bfloat16(v.x), hy = __float2bfloat16(v.y);
    __nv_bfloat16 hz = __float2bfloat16(v.z), hw = __float2bfloat16(v.w);
    __nv_bfloat16 lx = __float2bfloat16(v.x - __bfloat162float(hx));
    __nv_bfloat16 ly = __float2bfloat16(v.y - __bfloat162float(hy));
    __nv_bfloat16 lz = __float2bfloat16(v.z - __bfloat162float(hz));
    __nv_bfloat16 lw = __float2bfloat16(v.w - __bfloat162float(hw));
    hi[0] = pack2(hx, hy); hi[1] = pack2(hz, hw);
    lo[0] = pack2(lx, ly); lo[1] = pack2(lz, lw);
}

__device__ __forceinline__ float4 h4tof4(uint2 u) {
    __half2 a = *reinterpret_cast<__half2*>(&u.x);
    __half2 b = *reinterpret_cast<__half2*>(&u.y);
    float2 fa = __half22float2(a), fb = __half22float2(b);
    return make_float4(fa.x, fa.y, fb.x, fb.y);
}
__device__ __forceinline__ uint2 f4toh4(float4 v) {
    __half2 a = __floats2half2_rn(v.x, v.y);
    __half2 b = __floats2half2_rn(v.z, v.w);
    uint2 u;
    u.x = *reinterpret_cast<u32*>(&a);
    u.y = *reinterpret_cast<u32*>(&b);
    return u;
}

// SW128 swizzle: rows are 128B; 16B-chunk index XORed with (row & 7)
__device__ __forceinline__ u32 swz(u32 row, u32 chunk) {
    return row * 128u + ((chunk ^ (row & 7u)) << 4);
}

__device__ __forceinline__ void ldmA(u32* a, u32 addr) {
    asm volatile("ldmatrix.sync.aligned.m8n8.x4.shared.b16 {%0,%1,%2,%3}, [%4];"
                 : "=r"(a[0]), "=r"(a[1]), "=r"(a[2]), "=r"(a[3]) : "r"(addr));
}
__device__ __forceinline__ void ldmB4(u32* b, u32 addr) {   // two n8 B-frag pairs
    asm volatile("ldmatrix.sync.aligned.m8n8.x4.trans.shared.b16 {%0,%1,%2,%3}, [%4];"
                 : "=r"(b[0]), "=r"(b[1]), "=r"(b[2]), "=r"(b[3]) : "r"(addr));
}
__device__ __forceinline__ void mma16816(float* d, const u32* a, u32 b0, u32 b1) {
    asm volatile("mma.sync.aligned.m16n8k16.row.col.f32.bf16.bf16.f32 "
                 "{%0,%1,%2,%3}, {%4,%5,%6,%7}, {%8,%9}, {%0,%1,%2,%3};"
                 : "+f"(d[0]), "+f"(d[1]), "+f"(d[2]), "+f"(d[3])
                 : "r"(a[0]), "r"(a[1]), "r"(a[2]), "r"(a[3]), "r"(b0), "r"(b1));
}

// ---------------- kernels ----------------

// setup: zero cnt/pool/gcnt + embedding gather (padding_idx 0) -> splits + fp16
__global__ void k_setup(const int* __restrict__ x, const float* __restrict__ emb) {
    int tid = blockIdx.x * blockDim.x + threadIdx.x;   // NN*16 threads
    if (tid < NRNN)    g_cnt[tid] = 0;
    if (tid < NG * FD) g_pool[tid] = 0.f;
    if (tid < NG)      g_gcnt[tid] = 0;
    if (tid >= NN * 16) return;
    int n = tid >> 4, c = tid & 15;
    int tok = __ldg(&x[n]);
    float4 v = make_float4(0.f, 0.f, 0.f, 0.f);
    if (tok != 0) v = *(const float4*)(emb + (size_t)tok * FD + c * 4);
    size_t off = (size_t)n * FD + c * 4;
    u32 hi[2], lo[2];
    split4(v, hi, lo);
    *(uint2*)(g_Ah + off) = make_uint2(hi[0], hi[1]);
    *(uint2*)(g_Al + off) = make_uint2(lo[0], lo[1]);
    *(uint2*)(g_hh + off) = f4toh4(v);
}

// single-pass CSR: count + bucket-fill; also per-graph node counts
__global__ void k_fill(const int* __restrict__ src, const int* __restrict__ dst,
                       const int* __restrict__ et, const int* __restrict__ batch) {
    int e = blockIdx.x * blockDim.x + threadIdx.x;
    if (e < NN) atomicAdd(&g_gcnt[__ldg(&batch[e])], 1);
    if (e >= NE) return;
    int idx = __ldg(&et[e]) * NN + __ldg(&dst[e]);
    int pos = atomicAdd(&g_cnt[idx], 1);
    if (pos < BKT) g_bkt[idx * BKT + pos] = __ldg(&src[e]);
}

// atomic-free mean aggregation over fp16 features:
// acch[r][d] = fp16(mean over bucket of hh[src]); 16 lanes per segment
__global__ __launch_bounds__(256) void k_gather() {
    int g = threadIdx.x >> 4, l = threadIdx.x & 15;
    int p = blockIdx.x * 16 + g;
    if (p >= NRNN) return;
    int c = __ldg(&g_cnt[p]);
    if (c > BKT) c = BKT;
    const int* bp = g_bkt + (size_t)p * BKT;
    float4 v = make_float4(0.f, 0.f, 0.f, 0.f);
    int e = 0;
    for (; e + 3 < c; e += 4) {
        int s0 = __ldg(&bp[e]);
        int s1 = __ldg(&bp[e + 1]);
        int s2 = __ldg(&bp[e + 2]);
        int s3 = __ldg(&bp[e + 3]);
        float4 a = h4tof4(*(const uint2*)(g_hh + (size_t)s0 * FD + l * 4));
        float4 b = h4tof4(*(const uint2*)(g_hh + (size_t)s1 * FD + l * 4));
        float4 d = h4tof4(*(const uint2*)(g_hh + (size_t)s2 * FD + l * 4));
        float4 f = h4tof4(*(const uint2*)(g_hh + (size_t)s3 * FD + l * 4));
        v.x += (a.x + b.x) + (d.x + f.x);
        v.y += (a.y + b.y) + (d.y + f.y);
        v.z += (a.z + b.z) + (d.z + f.z);
        v.w += (a.w + b.w) + (d.w + f.w);
    }
    for (; e < c; e++) {
        int s0 = __ldg(&bp[e]);
        float4 a = h4tof4(*(const uint2*)(g_hh + (size_t)s0 * FD + l * 4));
        v.x += a.x; v.y += a.y; v.z += a.z; v.w += a.w;
    }
    float sc = 1.f / fmaxf((float)c, 1.f);
    v.x *= sc; v.y *= sc; v.z *= sc; v.w *= sc;
    *(uint2*)(g_acch + (size_t)p * FD + l * 4) = f4toh4(v);
}

// transform+combine via tensor cores (split-bf16, 3-pass):
// out = relu([h|a0|a1|a2] @ [Wroot;W0;W1;W2] + b),  M=NN, N=64, K=256.
// m0 plane from pre-split g_Ah/g_Al; planes 1-3 staged from fp16 g_acch
// (exact in-kernel split). Register double-buffered staging; SW128 smem.
#define SW_BYTES (512 * 128)             // weights hi+lo: [2][4 m][64 k] rows
#define SA_BYTES (256 * 128)             // A plane hi+lo: [2][128 row]
#define TR_SMEM (SW_BYTES + SA_BYTES)    // 98304

template <bool POOL>
__global__ __launch_bounds__(256, 2) void k_transform(
    const float* __restrict__ wrel,   // [3][64][64]
    const float* __restrict__ wroot,  // [64][64]
    const float* __restrict__ bias,   // [64]
    const int*   __restrict__ batch)  // [NN] (POOL only)
{
    extern __shared__ char smc[];
    char* sW = smc;                  // swizzled weights hi+lo
    char* sA = smc + SW_BYTES;       // swizzled A plane hi+lo

    int t = threadIdx.x;
    int lane = t & 31, w = t >> 5;
    int node0 = blockIdx.x * 128;

    // stage weights (once): fp32 -> hi/lo bf16, swizzled 8B stores
    for (int i = t; i < 4096; i += 256) {
        int m = i >> 10, rem = i & 1023;
        int k = rem >> 4, n4 = rem & 15;
        const float* srcp = (m == 0) ? (wroot + k * 64 + n4 * 4)
                                     : (wrel + ((size_t)(m - 1) * 64 + k) * 64 + n4 * 4);
        float4 v = *(const float4*)srcp;
        u32 hi[2], lo[2];
        split4(v, hi, lo);
        u32 rowH = (u32)(m * 64 + k);
        u32 rowL = rowH + 256;
        u32 within = (n4 & 1) * 8;
        *(uint2*)(sW + swz(rowH, (u32)(n4 >> 1)) + within) = make_uint2(hi[0], hi[1]);
        *(uint2*)(sW + swz(rowL, (u32)(n4 >> 1)) + within) = make_uint2(lo[0], lo[1]);
    }

    int qr = lane >> 2;          // fragment row 0..7
    int qc = (lane & 3) * 2;     // fragment col pair base

    float d[8][4];
    #pragma unroll
    for (int nb = 0; nb < 8; nb++) {
        float b0 = __ldg(&bias[nb * 8 + qc]);
        float b1 = __ldg(&bias[nb * 8 + qc + 1]);
        d[nb][0] = b0; d[nb][1] = b1; d[nb][2] = b0; d[nb][3] = b1;
    }

    u32 sA_base = (u32)__cvta_generic_to_shared(sA);
    u32 sW_base = (u32)__cvta_generic_to_shared(sW);
    u32 arow_lo = (u32)(w * 16 + (lane & 15));       // A frag row within split plane
    u32 asel    = (u32)(lane >> 4);                  // chunk half select

    // prefetch m0: pre-split bf16 planes, uint4 per thread x8
    // i = t + j*256; s = i>>10 (hi/lo), row = (i&1023)>>3, c8 = i&7
    uint4 p4[8];
    #pragma unroll
    for (int j = 0; j < 8; j++) {
        int i = t + j * 256;
        int s = i >> 10, rem = i & 1023;
        int row = rem >> 3, c8 = rem & 7;
        int node = node0 + row;
        uint4 v = make_uint4(0u, 0u, 0u, 0u);
        const __nv_bfloat16* gp = (s == 0) ? g_Ah : g_Al;
        if (node < NN) v = *(const uint4*)(gp + (size_t)node * FD + c8 * 8);
        p4[j] = v;
    }
    uint2 p2[8];   // fp16-plane prefetch: i = t+j*256; row=i>>4, c4=i&15

    for (int m = 0; m < 4; m++) {
        __syncthreads();     // prior plane's MMA reads done; sA reusable
        if (m == 0) {
            #pragma unroll
            for (int j = 0; j < 8; j++) {
                int i = t + j * 256;
                int s = i >> 10, rem = i & 1023;
                int row = rem >> 3, c8 = rem & 7;
                u32 srow = (u32)(s * 128 + row);
                *(uint4*)(sA + swz(srow, (u32)c8)) = p4[j];
            }
        } else {
            // convert fp16 -> float4 -> bf16 hi/lo split (exact), store swizzled
            #pragma unroll
            for (int j = 0; j < 8; j++) {
                int i = t + j * 256;
                int row = i >> 4, c4 = i & 15;
                float4 v = h4tof4(p2[j]);
                u32 hi[2], lo[2];
                split4(v, hi, lo);
                u32 within = (c4 & 1) * 8;
                *(uint2*)(sA + swz((u32)row,        (u32)(c4 >> 1)) + within) = make_uint2(hi[0], hi[1]);
                *(uint2*)(sA + swz((u32)row + 128u, (u32)(c4 >> 1)) + within) = make_uint2(lo[0], lo[1]);
            }
        }
        __syncthreads();
        // prefetch next plane (fp16 acc, rel index = m) while computing m
        if (m < 3) {
            const __half* gp = g_acch + (size_t)m * NN * FD;
            #pragma unroll
            for (int j = 0; j < 8; j++) {
                int i = t + j * 256;
                int row = i >> 4, c4 = i & 15;
                int node = node0 + row;
                uint2 v = make_uint2(0u, 0u);
                if (node < NN) v = *(const uint2*)(gp + (size_t)node * FD + c4 * 4);
                p2[j] = v;
            }
        }
        #pragma unroll
        for (int kb = 0; kb < 4; kb++) {
            u32 ah[4], al[4];
            u32 achunk = (u32)(kb * 2) + asel;
            ldmA(ah, sA_base + swz(arow_lo,        achunk));
            ldmA(al, sA_base + swz(arow_lo + 128u, achunk));
            u32 Bh[4][4], Bl[4][4];
            u32 brow = (u32)(m * 64 + kb * 16 + (lane & 15));
            #pragma unroll
            for (int nb2 = 0; nb2 < 4; nb2++) {
                u32 bchunk = (u32)(nb2 * 2) + asel;
                ldmB4(Bh[nb2], sW_base + swz(brow,        bchunk));
                ldmB4(Bl[nb2], sW_base + swz(brow + 256u, bchunk));
            }
            #pragma unroll
            for (int nb2 = 0; nb2 < 4; nb2++) {
                #pragma unroll
                for (int half = 0; half < 2; half++) {
                    float* dd = d[nb2 * 2 + half];
                    u32 bh0 = Bh[nb2][half * 2], bh1 = Bh[nb2][half * 2 + 1];
                    u32 bl0 = Bl[nb2][half * 2], bl1 = Bl[nb2][half * 2 + 1];
                    mma16816(dd, ah, bh0, bh1);
                    mma16816(dd, ah, bl0, bl1);
                    mma16816(dd, al, bh0, bh1);
                }
            }
        }
    }

    // epilogue: relu; POOL: red.v2 into g_pool; else write h splits + fp16
    int r0 = node0 + w * 16 + qr;
    int r1 = r0 + 8;
    if (POOL) {
        int b0v = (r0 < NN) ? __ldg(&batch[r0]) : 0;
        int b1v = (r1 < NN) ? __ldg(&batch[r1]) : 0;
        #pragma unroll
        for (int nb = 0; nb < 8; nb++) {
            int col = nb * 8 + qc;
            float o0 = fmaxf(d[nb][0], 0.f), o1 = fmaxf(d[nb][1], 0.f);
            float o2 = fmaxf(d[nb][2], 0.f), o3 = fmaxf(d[nb][3], 0.f);
            if (r0 < NN)
                asm volatile("red.global.add.v2.f32 [%0], {%1,%2};"
                             :: "l"(g_pool + (size_t)b0v * FD + col), "f"(o0), "f"(o1) : "memory");
            if (r1 < NN)
                asm volatile("red.global.add.v2.f32 [%0], {%1,%2};"
                             :: "l"(g_pool + (size_t)b1v * FD + col), "f"(o2), "f"(o3) : "memory");
        }
    } else {
        #pragma unroll
        for (int nb = 0; nb < 8; nb++) {
            int col = nb * 8 + qc;
            float o0 = fmaxf(d[nb][0], 0.f), o1 = fmaxf(d[nb][1], 0.f);
            float o2 = fmaxf(d[nb][2], 0.f), o3 = fmaxf(d[nb][3], 0.f);
            #pragma unroll
            for (int half = 0; half < 2; half++) {
                int node = half ? r1 : r0;
                if (node >= NN) continue;
                float x = half ? o2 : o0, y = half ? o3 : o1;
                size_t off = (size_t)node * FD + col;
                __nv_bfloat16 hx = __float2bfloat16(x), hy = __float2bfloat16(y);
                __nv_bfloat16 lx = __float2bfloat16(x - __bfloat162float(hx));
                __nv_bfloat16 ly = __float2bfloat16(y - __bfloat162float(hy));
                *(u32*)(g_Ah + off) = pack2(hx, hy);
                *(u32*)(g_Al + off) = pack2(lx, ly);
                __half2 hh = __floats2half2_rn(x, y);
                *(u32*)(g_hh + off) = *reinterpret_cast<u32*>(&hh);
            }
        }
    }
}

// final: logits[g] = (pool[g]/max(cnt,1)) @ lin_w + lin_b
__global__ void k_final(const float* __restrict__ lin_w, const float* __restrict__ lin_b,
                        float* __restrict__ out) {
    int g = blockIdx.x;          // 512 blocks
    int f = threadIdx.x;         // 64 threads
    float s = g_pool[g * FD + f] / fmaxf((float)g_gcnt[g], 1.f);
    float p0 = s * lin_w[f * NC + 0];
    float p1 = s * lin_w[f * NC + 1];
    #pragma unroll
    for (int off = 16; off > 0; off >>= 1) {
        p0 += __shfl_down_sync(0xffffffffu, p0, off);
        p1 += __shfl_down_sync(0xffffffffu, p1, off);
    }
    __shared__ float s0[2], s1[2];
    int w = f >> 5;
    if ((f & 31) == 0) { s0[w] = p0; s1[w] = p1; }
    __syncthreads();
    if (f == 0) {
        out[g * NC + 0] = s0[0] + s0[1] + lin_b[0];
        out[g * NC + 1] = s1[0] + s1[1] + lin_b[1];
    }
}

// ---------------- launch ----------------
extern "C" void kernel_launch(void* const* d_in, const int* in_sizes, int n_in,
                              void* d_out, int out_size) {
    const int*   x      = (const int*)  d_in[0];
    const int*   ei     = (const int*)  d_in[1];   // [2, NE]
    const int*   et     = (const int*)  d_in[2];
    const int*   batch  = (const int*)  d_in[3];
    const float* emb    = (const float*)d_in[4];
    const float* w1_rel = (const float*)d_in[5];
    const float* w1_root= (const float*)d_in[6];
    const float* b1     = (const float*)d_in[7];
    const float* w2_rel = (const float*)d_in[8];
    const float* w2_root= (const float*)d_in[9];
    const float* b2     = (const float*)d_in[10];
    const float* lin_w  = (const float*)d_in[11];
    const float* lin_b  = (const float*)d_in[12];
    float* out = (float*)d_out;

    const int* src = ei;
    const int* dst = ei + NE;

    static bool attr_done = false;
    if (!attr_done) {
        cudaFuncSetAttribute(k_transform<false>,
                             cudaFuncAttributeMaxDynamicSharedMemorySize, TR_SMEM);
        cudaFuncSetAttribute(k_transform<true>,
                             cudaFuncAttributeMaxDynamicSharedMemorySize, TR_SMEM);
        attr_done = true;
    }

    const int B = 256;
    int gb_nn16 = (NN * 16 + B - 1) / B;      // 3125
    int gb_ne   = (NE + B - 1) / B;           // 4883
    int gb_gth  = (NRNN + 15) / 16;           // 9375
    int gb_tr   = (NN + 127) / 128;           // 391

    k_setup<<<gb_nn16, B>>>(x, emb);
    k_fill<<<gb_ne, B>>>(src, dst, et, batch);

    // layer 1: fp16 mean-aggregate, then tensor-core transform+combine
    k_gather<<<gb_gth, B>>>();
    k_transform<false><<<gb_tr, 256, TR_SMEM>>>(w1_rel, w1_root, b1, nullptr);

    // layer 2: transform epilogue pools directly
    k_gather<<<gb_gth, B>>>();
    k_transform<true><<<gb_tr, 256, TR_SMEM>>>(w2_rel, w2_root, b2, batch);

    k_final<<<NG, 64>>>(lin_w, lin_b, out);
}